// round 4
// baseline (speedup 1.0000x reference)
#include <cuda_runtime.h>
#include <cstdint>

#define NN 8192
#define FF 8
#define JT 1024            // j-tile in shared (feature planes)

// ---- gemv config: 7 warps * 4 rows = 28 rows/block, 293 blocks = 1 wave @2 CTA/SM
#define GTPB 224
#define GRPW 4
#define GRPB 28
#define GGRID ((NN + GRPB - 1) / GRPB)   // 293
#define GCHUNK 64                        // j per chunk (lane = 2 j)
#define GNITER (NN / GCHUNK)             // 128
#define GIPT (JT / GCHUNK)               // 16

// ---- fid config: 64 tiles of 128, upper-triangular tile pairs
#define FTS 128
#define FT (NN / FTS)                    // 64
#define FGRID (FT * (FT + 1) / 2)        // 2080
#define RT9 0.94868329805051381f         // sqrt(0.9)

typedef unsigned long long ull;

__device__ float g_dense[NN * FF];       // message-passing result (static scratch)

// ---------------- f32x2 helpers ----------------
__device__ __forceinline__ ull fma2(ull a, ull b, ull c) {
    ull d; asm("fma.rn.f32x2 %0, %1, %2, %3;" : "=l"(d) : "l"(a), "l"(b), "l"(c)); return d;
}
__device__ __forceinline__ ull mul2(ull a, ull b) {
    ull d; asm("mul.rn.f32x2 %0, %1, %2;" : "=l"(d) : "l"(a), "l"(b)); return d;
}
__device__ __forceinline__ ull add2(ull a, ull b) {
    ull d; asm("add.rn.f32x2 %0, %1, %2;" : "=l"(d) : "l"(a), "l"(b)); return d;
}
__device__ __forceinline__ ull pack2(float lo, float hi) {
    ull d; asm("mov.b64 %0, {%1, %2};" : "=l"(d) : "f"(lo), "f"(hi)); return d;
}
__device__ __forceinline__ void unpack2(ull v, float& lo, float& hi) {
    asm("mov.b64 {%0, %1}, %2;" : "=f"(lo), "=f"(hi) : "l"(v));
}

// fast overflow-safe tanh / sigmoid
__device__ __forceinline__ float ftanh(float x) {
    float t = fabsf(x);
    float e = __expf(-2.0f * t);
    float r = __fdividef(1.0f - e, 1.0f + e);
    return copysignf(r, x);
}
__device__ __forceinline__ float fsigmoid(float x) {
    float e = __expf(-fabsf(x));
    float p = __fdividef(1.0f, 1.0f + e);
    return (x >= 0.0f) ? p : 1.0f - p;
}

// =================================================================
// Pass 1: g_dense = A @ X   (pure dense weighted sum, DRAM-bound)
// =================================================================
__global__ void __launch_bounds__(GTPB, 2)
gemv_kernel(const float* __restrict__ A, const float* __restrict__ X)
{
    __shared__ __align__(16) float2 shx[4][JT];   // feature-pair planes

    const int tid  = threadIdx.x;
    const int lane = tid & 31;
    const int warp = tid >> 5;

    int i0 = blockIdx.x * GRPB + warp * GRPW;
    if (i0 > NN - GRPW) i0 = NN - GRPW;   // clamp: duplicate rows write identical data

    ull acc[GRPW][4];
    #pragma unroll
    for (int r = 0; r < GRPW; r++)
        #pragma unroll
        for (int kk = 0; kk < 4; kk++) acc[r][kk] = 0ull;

    uint32_t sb;
    asm("{ .reg .u64 t; cvta.to.shared.u64 t, %1; cvt.u32.u64 %0, t; }"
        : "=r"(sb) : "l"(&shx[0][0]));

    const float* Ab = A + (size_t)i0 * NN + lane * 2;

    // depth-4 A prefetch ring (distance ~3 chunks > DRAM latency)
    ull buf0[GRPW], buf1[GRPW], buf2[GRPW], buf3[GRPW];

    #define LDA(n, buf)                                                        \
        do {                                                                   \
            const float* p_ = Ab + (size_t)(n) * GCHUNK;                       \
            _Pragma("unroll")                                                  \
            for (int r_ = 0; r_ < GRPW; r_++)                                  \
                (buf)[r_] = __ldg(reinterpret_cast<const ull*>(p_ + (size_t)r_ * NN)); \
        } while (0)

    #define COMPUTE(jj, buf)                                                   \
        do {                                                                   \
            ull Pl_[4], Ph_[4];                                                \
            _Pragma("unroll")                                                  \
            for (int kk_ = 0; kk_ < 4; kk_++) {                                \
                asm("ld.shared.v2.b64 {%0, %1}, [%2];"                         \
                    : "=l"(Pl_[kk_]), "=l"(Ph_[kk_])                           \
                    : "r"(sb + (uint32_t)(kk_ * (JT * 8) + (jj) * 8)));        \
            }                                                                  \
            _Pragma("unroll")                                                  \
            for (int r_ = 0; r_ < GRPW; r_++) {                                \
                float a0_, a1_;                                                \
                unpack2((buf)[r_], a0_, a1_);                                  \
                ull w0_ = pack2(a0_, a0_);                                     \
                ull w1_ = pack2(a1_, a1_);                                     \
                _Pragma("unroll")                                              \
                for (int kk_ = 0; kk_ < 4; kk_++) {                            \
                    acc[r_][kk_] = fma2(w0_, Pl_[kk_], acc[r_][kk_]);          \
                    acc[r_][kk_] = fma2(w1_, Ph_[kk_], acc[r_][kk_]);          \
                }                                                              \
            }                                                                  \
        } while (0)

    LDA(0, buf0); LDA(1, buf1); LDA(2, buf2); LDA(3, buf3);

    for (int t = 0; t < NN / JT; t++) {
        __syncthreads();  // previous tile fully consumed
        const int t0 = t * JT;
        for (int j = tid; j < JT; j += GTPB) {
            const float4* xp = reinterpret_cast<const float4*>(X + (size_t)(t0 + j) * FF);
            float4 a = __ldg(xp), b = __ldg(xp + 1);
            shx[0][j] = make_float2(a.x, a.y);
            shx[1][j] = make_float2(a.z, a.w);
            shx[2][j] = make_float2(b.x, b.y);
            shx[3][j] = make_float2(b.z, b.w);
        }
        __syncthreads();

        #pragma unroll 1
        for (int cc = 0; cc < GIPT; cc += 4) {
            const int n = t * GIPT + cc;
            const int jj = cc * GCHUNK + lane * 2;
            COMPUTE(jj,                buf0);
            { int np = n + 4; if (np >= GNITER) np -= GNITER; LDA(np, buf0); }
            COMPUTE(jj + GCHUNK,       buf1);
            { int np = n + 5; if (np >= GNITER) np -= GNITER; LDA(np, buf1); }
            COMPUTE(jj + 2 * GCHUNK,   buf2);
            { int np = n + 6; if (np >= GNITER) np -= GNITER; LDA(np, buf2); }
            COMPUTE(jj + 3 * GCHUNK,   buf3);
            { int np = n + 7; if (np >= GNITER) np -= GNITER; LDA(np, buf3); }
        }
    }
    #undef LDA
    #undef COMPUTE

    // warp butterfly reduction
    #pragma unroll
    for (int r = 0; r < GRPW; r++)
        #pragma unroll
        for (int kk = 0; kk < 4; kk++) {
            ull v = acc[r][kk];
            #pragma unroll
            for (int o = 16; o; o >>= 1)
                v = add2(v, __shfl_xor_sync(0xffffffffu, v, o));
            acc[r][kk] = v;
        }

    if (lane < GRPW) {
        float2* out = reinterpret_cast<float2*>(&g_dense[(size_t)(i0 + lane) * FF]);
        #pragma unroll
        for (int kk = 0; kk < 4; kk++) {
            float lo, hi;
            unpack2(acc[lane][kk], lo, hi);
            out[kk] = make_float2(lo, hi);
        }
    }
}

// =================================================================
// Pass 2: sparse fidelity corrections (i<j tile pairs, ~1e-4 hit rate)
// fid ⟺ |xn_i · xn_j| >= sqrt(0.9); on hit add (1-A_ij)*x_j to row i
// (and symmetric), making the effective weight exactly 1.
// =================================================================
__global__ void __launch_bounds__(FTS, 8)
fid_kernel(const float* __restrict__ A, const float* __restrict__ X)
{
    // decode upper-triangular tile pair (ti <= tj)
    int b = blockIdx.x, ti = 0, rem = b;
    while (rem >= FT - ti) { rem -= FT - ti; ti++; }
    const int tj = ti + rem;

    __shared__ __align__(16) ull pa[4][FTS], pb[4][FTS];  // normalized feature pairs

    const int t = threadIdx.x;   // 0..127: local i within tile ti
    {
        const float4* xp = reinterpret_cast<const float4*>(X + (size_t)(ti * FTS + t) * FF);
        float4 a = __ldg(xp), c = __ldg(xp + 1);
        float ss = a.x*a.x + a.y*a.y + a.z*a.z + a.w*a.w
                 + c.x*c.x + c.y*c.y + c.z*c.z + c.w*c.w;
        float inv = 1.0f / (sqrtf(ss) + 1e-12f);
        pa[0][t] = pack2(a.x*inv, a.y*inv);
        pa[1][t] = pack2(a.z*inv, a.w*inv);
        pa[2][t] = pack2(c.x*inv, c.y*inv);
        pa[3][t] = pack2(c.z*inv, c.w*inv);
    }
    {
        const float4* xp = reinterpret_cast<const float4*>(X + (size_t)(tj * FTS + t) * FF);
        float4 a = __ldg(xp), c = __ldg(xp + 1);
        float ss = a.x*a.x + a.y*a.y + a.z*a.z + a.w*a.w
                 + c.x*c.x + c.y*c.y + c.z*c.z + c.w*c.w;
        float inv = 1.0f / (sqrtf(ss) + 1e-12f);
        pb[0][t] = pack2(a.x*inv, a.y*inv);
        pb[1][t] = pack2(a.z*inv, a.w*inv);
        pb[2][t] = pack2(c.x*inv, c.y*inv);
        pb[3][t] = pack2(c.z*inv, c.w*inv);
    }
    __syncthreads();

    const ull x0 = pa[0][t], x1 = pa[1][t], x2 = pa[2][t], x3 = pa[3][t];
    const int jstart = (ti == tj) ? (t + 1) : 0;   // strict upper triangle on diag tiles

    for (int j = jstart; j < FTS; j++) {
        ull d = mul2(x0, pb[0][j]);   // smem broadcast: all lanes same j
        d = fma2(x1, pb[1][j], d);
        d = fma2(x2, pb[2][j], d);
        d = fma2(x3, pb[3][j], d);
        float lo, hi; unpack2(d, lo, hi);
        float s = lo + hi;
        if (fabsf(s) >= RT9) {        // rare (~1e-4)
            const int gi = ti * FTS + t;
            const int gj = tj * FTS + j;
            float aij = __ldg(A + (size_t)gi * NN + gj);
            float aji = __ldg(A + (size_t)gj * NN + gi);
            const float* xj = X + (size_t)gj * FF;
            const float* xi = X + (size_t)gi * FF;
            #pragma unroll
            for (int k = 0; k < FF; k++)
                atomicAdd(&g_dense[(size_t)gi * FF + k], (1.0f - aij) * __ldg(xj + k));
            #pragma unroll
            for (int k = 0; k < FF; k++)
                atomicAdd(&g_dense[(size_t)gj * FF + k], (1.0f - aji) * __ldg(xi + k));
        }
    }
}

// =================================================================
// Pass 3: per-row MLP + sigmoid head (weights staged in smem)
// =================================================================
#define NW_TOT 785
__global__ void __launch_bounds__(64)
mlp_kernel(const float* __restrict__ Wfm, const float* __restrict__ bfm,
           const float* __restrict__ Wc1, const float* __restrict__ bc1,
           const float* __restrict__ Wp1, const float* __restrict__ bp1,
           const float* __restrict__ Wc2, const float* __restrict__ bc2,
           const float* __restrict__ Wp2, const float* __restrict__ bp2,
           const float* __restrict__ Wc3, const float* __restrict__ bc3,
           const float* __restrict__ Wh,  const float* __restrict__ bh,
           float* __restrict__ out)
{
    __shared__ float w[NW_TOT];
    const int tid = threadIdx.x;

    // cooperative weight staging
    struct Seg { const float* src; int off, n; };
    const Seg segs[14] = {
        {Wfm,   0, 128}, {bfm, 128, 16}, {Wc1, 144, 256}, {bc1, 400, 16},
        {Wp1, 416, 192}, {bp1, 608, 12}, {Wc2, 620,  96}, {bc2, 716,  8},
        {Wp2, 724,  32}, {bp2, 756,  4}, {Wc3, 760,  16}, {bc3, 776,  4},
        {Wh,  780,   4}, {bh,  784,  1}
    };
    #pragma unroll
    for (int s = 0; s < 14; s++)
        for (int k = tid; k < segs[s].n; k += 64)
            w[segs[s].off + k] = __ldg(segs[s].src + k);
    __syncthreads();

    const int i = blockIdx.x * 64 + tid;

    float v[16], h[16];
    #pragma unroll
    for (int k = 0; k < 8; k++) v[k] = g_dense[(size_t)i * FF + k];

    #define LAYER(IN, OUT, WOFF, BOFF, src, dst)                          \
        do {                                                              \
            _Pragma("unroll")                                             \
            for (int j_ = 0; j_ < (OUT); j_++) {                          \
                float s_ = w[(BOFF) + j_];                                \
                _Pragma("unroll")                                         \
                for (int k_ = 0; k_ < (IN); k_++)                         \
                    s_ = fmaf((src)[k_], w[(WOFF) + k_ * (OUT) + j_], s_);\
                (dst)[j_] = ftanh(s_);                                    \
            }                                                             \
        } while (0)

    LAYER(8, 16,   0, 128, v, h);
    LAYER(16, 16, 144, 400, h, v);
    LAYER(16, 12, 416, 608, v, h);
    LAYER(12, 8,  620, 716, h, v);
    LAYER(8, 4,   724, 756, v, h);
    LAYER(4, 4,   760, 776, h, v);
    #undef LAYER

    float z = w[784];
    #pragma unroll
    for (int k = 0; k < 4; k++)
        z = fmaf(v[k], w[780 + k], z);
    out[i] = fsigmoid(z);
}

extern "C" void kernel_launch(void* const* d_in, const int* in_sizes, int n_in,
                              void* d_out, int out_size)
{
    const float* A = (const float*)d_in[0];
    const float* X = (const float*)d_in[1];

    gemv_kernel<<<GGRID, GTPB>>>(A, X);
    fid_kernel<<<FGRID, FTS>>>(A, X);
    mlp_kernel<<<NN / 64, 64>>>(
        (const float*)d_in[2],  (const float*)d_in[3],
        (const float*)d_in[4],  (const float*)d_in[5],
        (const float*)d_in[6],  (const float*)d_in[7],
        (const float*)d_in[8],  (const float*)d_in[9],
        (const float*)d_in[10], (const float*)d_in[11],
        (const float*)d_in[12], (const float*)d_in[13],
        (const float*)d_in[14], (const float*)d_in[15],
        (float*)d_out);
}

// round 5
// speedup vs baseline: 1.0913x; 1.0913x over previous
#include <cuda_runtime.h>
#include <cstdint>

#define NN 8192
#define FF 8
#define JT 1024                     // j-tile in shared
#define GTPB 224                    // 7 warps
#define GRPW 4                      // rows per warp
#define GRPB 28                     // rows per block
#define GGRID ((NN + GRPB - 1) / GRPB)   // 293
#define GCH 128                     // j per chunk (lane owns 4 consecutive j)
#define GNCH (NN / GCH)             // 64 chunks total
#define FTS 128
#define FT (NN / FTS)               // 64
#define FGRID (FT * (FT + 1) / 2)   // 2080
#define RT9 0.94868329805051381f    // sqrt(0.9)

typedef unsigned long long ull;

__device__ float g_dense[NN * FF];

// ---------------- f32x2 helpers ----------------
__device__ __forceinline__ ull fma2(ull a, ull b, ull c) {
    ull d; asm("fma.rn.f32x2 %0, %1, %2, %3;" : "=l"(d) : "l"(a), "l"(b), "l"(c)); return d;
}
__device__ __forceinline__ ull mul2(ull a, ull b) {
    ull d; asm("mul.rn.f32x2 %0, %1, %2;" : "=l"(d) : "l"(a), "l"(b)); return d;
}
__device__ __forceinline__ ull add2(ull a, ull b) {
    ull d; asm("add.rn.f32x2 %0, %1, %2;" : "=l"(d) : "l"(a), "l"(b)); return d;
}
__device__ __forceinline__ ull pack2(float lo, float hi) {
    ull d; asm("mov.b64 %0, {%1, %2};" : "=l"(d) : "f"(lo), "f"(hi)); return d;
}
__device__ __forceinline__ void unpack2(ull v, float& lo, float& hi) {
    asm("mov.b64 {%0, %1}, %2;" : "=f"(lo), "=f"(hi) : "l"(v));
}
__device__ __forceinline__ float ftanh(float x) {
    float t = fabsf(x);
    float e = __expf(-2.0f * t);
    float r = __fdividef(1.0f - e, 1.0f + e);
    return copysignf(r, x);
}
__device__ __forceinline__ float fsigmoid(float x) {
    float e = __expf(-fabsf(x));
    float p = __fdividef(1.0f, 1.0f + e);
    return (x >= 0.0f) ? p : 1.0f - p;
}

// =================================================================
// Pass 1: g_dense = A @ X  (dense weighted row-sum, DRAM-bound)
// smem layout (position-permuted): for tile-local chunk c (0..7),
// piece q (0..7), lane l (0..31): 16B at  c*4096 + q*512 + l*16.
// Node j (tile-local): c=j>>7, l=(j>>2)&31, r=j&3; its features
// f[0:4) at q=2r, f[4:8) at q=2r+1.  -> reads are 16B-lane-stride
// conflict-free while lane's A j's are consecutive (LDG.128).
// =================================================================
__global__ void __launch_bounds__(GTPB, 2)
gemv_kernel(const float* __restrict__ A, const float* __restrict__ X)
{
    __shared__ __align__(16) ull shx[JT * 4];   // 32 KB

    const int tid  = threadIdx.x;
    const int lane = tid & 31;
    const int warp = tid >> 5;

    int i0 = blockIdx.x * GRPB + warp * GRPW;
    if (i0 > NN - GRPW) i0 = NN - GRPW;   // duplicate rows write identical data

    ull acc[GRPW][4];
    #pragma unroll
    for (int r = 0; r < GRPW; r++)
        #pragma unroll
        for (int kk = 0; kk < 4; kk++) acc[r][kk] = 0ull;

    uint32_t sb;
    asm("{ .reg .u64 t; cvta.to.shared.u64 t, %1; cvt.u32.u64 %0, t; }"
        : "=r"(sb) : "l"(&shx[0]));

    const float* Ab = A + (size_t)i0 * NN + lane * 4;

    float4 b0[GRPW], b1[GRPW], b2[GRPW], b3[GRPW];

    #define LDA(n, B)                                                          \
        do {                                                                   \
            const float* p_ = Ab + (size_t)(n) * GCH;                          \
            _Pragma("unroll")                                                  \
            for (int r_ = 0; r_ < GRPW; r_++)                                  \
                (B)[r_] = __ldcs(reinterpret_cast<const float4*>(p_ + (size_t)r_ * NN)); \
        } while (0)

    #define LDAW(n, B) do { int np_ = (n); if (np_ >= GNCH) np_ -= GNCH; LDA(np_, B); } while (0)

    // one j-pair worth of compute: pieces (pa0,pa1)=(f01,f23), (pb0,pb1)=(f45,f67)
    #define HALF(B, c0, c1, q0off)                                             \
        do {                                                                   \
            ull pa0_, pa1_, pb0_, pb1_, pc0_, pc1_, pd0_, pd1_;                \
            asm("ld.shared.v2.b64 {%0, %1}, [%2];" : "=l"(pa0_), "=l"(pa1_)    \
                : "r"(ba_ + (q0off)));                                         \
            asm("ld.shared.v2.b64 {%0, %1}, [%2];" : "=l"(pb0_), "=l"(pb1_)    \
                : "r"(ba_ + (q0off) + 512));                                   \
            asm("ld.shared.v2.b64 {%0, %1}, [%2];" : "=l"(pc0_), "=l"(pc1_)    \
                : "r"(ba_ + (q0off) + 1024));                                  \
            asm("ld.shared.v2.b64 {%0, %1}, [%2];" : "=l"(pd0_), "=l"(pd1_)    \
                : "r"(ba_ + (q0off) + 1536));                                  \
            _Pragma("unroll")                                                  \
            for (int r_ = 0; r_ < GRPW; r_++) {                                \
                ull w0_ = pack2((B)[r_].c0, (B)[r_].c0);                       \
                acc[r_][0] = fma2(w0_, pa0_, acc[r_][0]);                      \
                acc[r_][1] = fma2(w0_, pa1_, acc[r_][1]);                      \
                acc[r_][2] = fma2(w0_, pb0_, acc[r_][2]);                      \
                acc[r_][3] = fma2(w0_, pb1_, acc[r_][3]);                      \
                ull w1_ = pack2((B)[r_].c1, (B)[r_].c1);                       \
                acc[r_][0] = fma2(w1_, pc0_, acc[r_][0]);                      \
                acc[r_][1] = fma2(w1_, pc1_, acc[r_][1]);                      \
                acc[r_][2] = fma2(w1_, pd0_, acc[r_][2]);                      \
                acc[r_][3] = fma2(w1_, pd1_, acc[r_][3]);                      \
            }                                                                  \
        } while (0)

    #define COMPUTE(cb, B)                                                     \
        do {                                                                   \
            const uint32_t ba_ = sb + (uint32_t)(cb) + lane * 16;              \
            HALF(B, x, y, 0);        /* j0 (q0,q1), j1 (q2,q3) */              \
            HALF(B, z, w, 2048);     /* j2 (q4,q5), j3 (q6,q7) */              \
        } while (0)

    LDA(0, b0); LDA(1, b1); LDA(2, b2); LDA(3, b3);

    #pragma unroll 1
    for (int g = 0; g < 16; g++) {          // 4 chunks per group
        if ((g & 1) == 0) {
            __syncthreads();                // previous tile consumed
            const int t0 = (g >> 1) * JT;
            for (int j = tid; j < JT; j += GTPB) {
                const float4* xp = reinterpret_cast<const float4*>(X + (size_t)(t0 + j) * FF);
                float4 a = __ldg(xp), b = __ldg(xp + 1);
                const int c = j >> 7, l = (j >> 2) & 31, r = j & 3;
                ull* dst = &shx[(size_t)c * 512 + (size_t)(2 * r) * 64 + (size_t)l * 2];
                dst[0]  = pack2(a.x, a.y);
                dst[1]  = pack2(a.z, a.w);
                dst[64] = pack2(b.x, b.y);
                dst[65] = pack2(b.z, b.w);
            }
            __syncthreads();
        }
        const int n = g * 4;
        COMPUTE(((n    ) & 7) * 4096, b0); LDAW(n + 4, b0);
        COMPUTE(((n + 1) & 7) * 4096, b1); LDAW(n + 5, b1);
        COMPUTE(((n + 2) & 7) * 4096, b2); LDAW(n + 6, b2);
        COMPUTE(((n + 3) & 7) * 4096, b3); LDAW(n + 7, b3);
    }
    #undef LDA
    #undef LDAW
    #undef HALF
    #undef COMPUTE

    // warp butterfly reduction
    #pragma unroll
    for (int r = 0; r < GRPW; r++)
        #pragma unroll
        for (int kk = 0; kk < 4; kk++) {
            ull v = acc[r][kk];
            #pragma unroll
            for (int o = 16; o; o >>= 1)
                v = add2(v, __shfl_xor_sync(0xffffffffu, v, o));
            acc[r][kk] = v;
        }

    if (lane < GRPW) {
        float2* out = reinterpret_cast<float2*>(&g_dense[(size_t)(i0 + lane) * FF]);
        #pragma unroll
        for (int kk = 0; kk < 4; kk++) {
            float lo, hi;
            unpack2(acc[lane][kk], lo, hi);
            out[kk] = make_float2(lo, hi);
        }
    }
}

// =================================================================
// Pass 2: sparse fidelity corrections (runs after gemv; atomics
// into g_dense). fid ⟺ |xn_i · xn_j| >= sqrt(0.9); on hit the
// effective weight becomes exactly 1: add (1-A)*x.
// =================================================================
__global__ void __launch_bounds__(FTS, 8)
fid_kernel(const float* __restrict__ A, const float* __restrict__ X)
{
    int b = blockIdx.x, ti = 0, rem = b;
    while (rem >= FT - ti) { rem -= FT - ti; ti++; }
    const int tj = ti + rem;

    __shared__ __align__(16) ull pb[FTS * 4];   // 32B per j, contiguous

    const int t = threadIdx.x;

    // own row (i side) normalized, in registers
    ull xi0, xi1, xi2, xi3;
    {
        const float4* xp = reinterpret_cast<const float4*>(X + (size_t)(ti * FTS + t) * FF);
        float4 a = __ldg(xp), c = __ldg(xp + 1);
        float ss = a.x*a.x + a.y*a.y + a.z*a.z + a.w*a.w
                 + c.x*c.x + c.y*c.y + c.z*c.z + c.w*c.w;
        float inv = 1.0f / (sqrtf(ss) + 1e-12f);
        xi0 = pack2(a.x*inv, a.y*inv);
        xi1 = pack2(a.z*inv, a.w*inv);
        xi2 = pack2(c.x*inv, c.y*inv);
        xi3 = pack2(c.z*inv, c.w*inv);
    }
    // j side tile normalized into smem
    {
        const float4* xp = reinterpret_cast<const float4*>(X + (size_t)(tj * FTS + t) * FF);
        float4 a = __ldg(xp), c = __ldg(xp + 1);
        float ss = a.x*a.x + a.y*a.y + a.z*a.z + a.w*a.w
                 + c.x*c.x + c.y*c.y + c.z*c.z + c.w*c.w;
        float inv = 1.0f / (sqrtf(ss) + 1e-12f);
        pb[t*4 + 0] = pack2(a.x*inv, a.y*inv);
        pb[t*4 + 1] = pack2(a.z*inv, a.w*inv);
        pb[t*4 + 2] = pack2(c.x*inv, c.y*inv);
        pb[t*4 + 3] = pack2(c.z*inv, c.w*inv);
    }
    __syncthreads();

    uint32_t pbb;
    asm("{ .reg .u64 t; cvta.to.shared.u64 t, %1; cvt.u32.u64 %0, t; }"
        : "=r"(pbb) : "l"(&pb[0]));

    const int jstart = (ti == tj) ? (t + 1) : 0;

    #pragma unroll 4
    for (int j = jstart; j < FTS; j++) {
        ull q0, q1, q2, q3;
        asm("ld.shared.v2.b64 {%0, %1}, [%2];" : "=l"(q0), "=l"(q1)
            : "r"(pbb + (uint32_t)j * 32));
        asm("ld.shared.v2.b64 {%0, %1}, [%2];" : "=l"(q2), "=l"(q3)
            : "r"(pbb + (uint32_t)j * 32 + 16));
        ull d = mul2(xi0, q0);
        d = fma2(xi1, q1, d);
        d = fma2(xi2, q2, d);
        d = fma2(xi3, q3, d);
        float lo, hi; unpack2(d, lo, hi);
        float s = lo + hi;
        if (fabsf(s) >= RT9) {              // rare (~1e-4)
            const int gi = ti * FTS + t;
            const int gj = tj * FTS + j;
            float aij = __ldg(A + (size_t)gi * NN + gj);
            float aji = __ldg(A + (size_t)gj * NN + gi);
            const float* xj = X + (size_t)gj * FF;
            const float* xi = X + (size_t)gi * FF;
            #pragma unroll
            for (int k = 0; k < FF; k++)
                atomicAdd(&g_dense[(size_t)gi * FF + k], (1.0f - aij) * __ldg(xj + k));
            #pragma unroll
            for (int k = 0; k < FF; k++)
                atomicAdd(&g_dense[(size_t)gj * FF + k], (1.0f - aji) * __ldg(xi + k));
        }
    }
}

// =================================================================
// Pass 3: per-row MLP + sigmoid head (weights staged in smem)
// =================================================================
#define NW_TOT 785
__global__ void __launch_bounds__(64)
mlp_kernel(const float* __restrict__ Wfm, const float* __restrict__ bfm,
           const float* __restrict__ Wc1, const float* __restrict__ bc1,
           const float* __restrict__ Wp1, const float* __restrict__ bp1,
           const float* __restrict__ Wc2, const float* __restrict__ bc2,
           const float* __restrict__ Wp2, const float* __restrict__ bp2,
           const float* __restrict__ Wc3, const float* __restrict__ bc3,
           const float* __restrict__ Wh,  const float* __restrict__ bh,
           float* __restrict__ out)
{
    __shared__ float w[NW_TOT];
    const int tid = threadIdx.x;

    struct Seg { const float* src; int off, n; };
    const Seg segs[14] = {
        {Wfm,   0, 128}, {bfm, 128, 16}, {Wc1, 144, 256}, {bc1, 400, 16},
        {Wp1, 416, 192}, {bp1, 608, 12}, {Wc2, 620,  96}, {bc2, 716,  8},
        {Wp2, 724,  32}, {bp2, 756,  4}, {Wc3, 760,  16}, {bc3, 776,  4},
        {Wh,  780,   4}, {bh,  784,  1}
    };
    #pragma unroll
    for (int s = 0; s < 14; s++)
        for (int k = tid; k < segs[s].n; k += 64)
            w[segs[s].off + k] = __ldg(segs[s].src + k);
    __syncthreads();

    const int i = blockIdx.x * 64 + tid;

    float v[16], h[16];
    #pragma unroll
    for (int k = 0; k < 8; k++) v[k] = g_dense[(size_t)i * FF + k];

    #define LAYER(IN, OUT, WOFF, BOFF, src, dst)                          \
        do {                                                              \
            _Pragma("unroll")                                             \
            for (int j_ = 0; j_ < (OUT); j_++) {                          \
                float s_ = w[(BOFF) + j_];                                \
                _Pragma("unroll")                                         \
                for (int k_ = 0; k_ < (IN); k_++)                         \
                    s_ = fmaf((src)[k_], w[(WOFF) + k_ * (OUT) + j_], s_);\
                (dst)[j_] = ftanh(s_);                                    \
            }                                                             \
        } while (0)

    LAYER(8, 16,   0, 128, v, h);
    LAYER(16, 16, 144, 400, h, v);
    LAYER(16, 12, 416, 608, v, h);
    LAYER(12, 8,  620, 716, h, v);
    LAYER(8, 4,   724, 756, v, h);
    LAYER(4, 4,   760, 776, h, v);
    #undef LAYER

    float z = w[784];
    #pragma unroll
    for (int k = 0; k < 4; k++)
        z = fmaf(v[k], w[780 + k], z);
    out[i] = fsigmoid(z);
}

extern "C" void kernel_launch(void* const* d_in, const int* in_sizes, int n_in,
                              void* d_out, int out_size)
{
    const float* A = (const float*)d_in[0];
    const float* X = (const float*)d_in[1];

    gemv_kernel<<<GGRID, GTPB>>>(A, X);
    fid_kernel<<<FGRID, FTS>>>(A, X);
    mlp_kernel<<<NN / 64, 64>>>(
        (const float*)d_in[2],  (const float*)d_in[3],
        (const float*)d_in[4],  (const float*)d_in[5],
        (const float*)d_in[6],  (const float*)d_in[7],
        (const float*)d_in[8],  (const float*)d_in[9],
        (const float*)d_in[10], (const float*)d_in[11],
        (const float*)d_in[12], (const float*)d_in[13],
        (const float*)d_in[14], (const float*)d_in[15],
        (float*)d_out);
}